// round 1
// baseline (speedup 1.0000x reference)
#include <cuda_runtime.h>

#define NN 100000
#define NE 3200000
#define H  64

// -------- device scratch (no allocations allowed) --------
__device__ float g_deg[NN];
__device__ float g_dis[NN];
__device__ float g_h  [NN * H];   // current node features (h1, then h2)
__device__ float g_tmp[NN * H];   // x@W (pre-aggregation messages)

// -------- degree / norm --------
__global__ void k_init_deg() {
    int i = blockIdx.x * blockDim.x + threadIdx.x;
    if (i < NN) g_deg[i] = 1.0f;          // self-loop contribution
}

__global__ void k_deg(const int* __restrict__ dst) {
    int e = blockIdx.x * blockDim.x + threadIdx.x;
    if (e < NE) atomicAdd(&g_deg[dst[e]], 1.0f);
}

__global__ void k_dis() {
    int i = blockIdx.x * blockDim.x + threadIdx.x;
    if (i < NN) g_dis[i] = rsqrtf(g_deg[i]);   // deg >= 1 always
}

// -------- layer 1: tmp = x@W1 ; h = tmp*dis^2 (self-loop seed) --------
__global__ void k_xw1(const float* __restrict__ x, const float* __restrict__ W1) {
    int t = blockIdx.x * blockDim.x + threadIdx.x;
    if (t >= NN * H) return;
    int i = t >> 6, j = t & 63;
    float4 xv = *reinterpret_cast<const float4*>(x + (size_t)i * 4);
    float s = xv.x * W1[j] + xv.y * W1[64 + j] + xv.z * W1[128 + j] + xv.w * W1[192 + j];
    g_tmp[t] = s;
    float dd = g_dis[i];
    g_h[t] = s * dd * dd;
}

// -------- scatter: h[dst] += tmp[src] * dis[src]*dis[dst] --------
__global__ void k_scatter(const int* __restrict__ src, const int* __restrict__ dst) {
    long long t = (long long)blockIdx.x * blockDim.x + threadIdx.x;
    if (t >= (long long)NE * H) return;
    int e = (int)(t >> 6), j = (int)(t & 63);
    int s = src[e], d = dst[e];
    float v = g_tmp[s * H + j] * (g_dis[s] * g_dis[d]);
    atomicAdd(&g_h[d * H + j], v);
}

// -------- h = relu(h + b) --------
__global__ void k_relu_bias(const float* __restrict__ b) {
    int t = blockIdx.x * blockDim.x + threadIdx.x;
    if (t >= NN * H) return;
    float v = g_h[t] + b[t & 63];
    g_h[t] = v > 0.f ? v : 0.f;
}

// -------- layer 2 dense part: tmp = h@W2 ; h(seed) = tmp*dis^2 --------
// 256 threads / block, 16 nodes / block. Each block only touches its own rows
// of g_h (loaded to smem before overwrite), so in-place seeding is safe.
__global__ void k_gemm2(const float* __restrict__ W2) {
    __shared__ float sW[64 * 64];
    __shared__ float sIn[16 * 64];
    int tid = threadIdx.x;
    int nb = blockIdx.x * 16;
    for (int idx = tid; idx < 4096; idx += 256) sW[idx] = W2[idx];
    for (int idx = tid; idx < 1024; idx += 256) sIn[idx] = g_h[nb * 64 + idx];
    __syncthreads();
    int col = tid & 63, ng = tid >> 6;  // ng in 0..3
    float a0 = 0.f, a1 = 0.f, a2 = 0.f, a3 = 0.f;
#pragma unroll 8
    for (int k = 0; k < 64; k++) {
        float w = sW[k * 64 + col];
        a0 += sIn[(ng     ) * 64 + k] * w;
        a1 += sIn[(ng +  4) * 64 + k] * w;
        a2 += sIn[(ng +  8) * 64 + k] * w;
        a3 += sIn[(ng + 12) * 64 + k] * w;
    }
    float accs[4] = {a0, a1, a2, a3};
#pragma unroll
    for (int m = 0; m < 4; m++) {
        int node = nb + ng + 4 * m;
        float dd = g_dis[node];
        int o = node * 64 + col;
        g_tmp[o] = accs[m];
        g_h[o]   = accs[m] * dd * dd;
    }
}

// -------- edge MLP: per edge, [h_src|h_dst|ea](132) @ Wm1(132x64) -> relu -> @Wm2(64) --------
// Tile: 64 edges x 64 cols per block of 256 threads; 4x4 register micro-tile.
// smem: sW = Wm1 (132x64), sA = edge_in tile stored k-major [132][64 edges].
__global__ void k_mlp(const int*   __restrict__ src, const int* __restrict__ dst,
                      const float* __restrict__ ea,
                      const float* __restrict__ Wm1, const float* __restrict__ bm1,
                      const float* __restrict__ Wm2, const float* __restrict__ bm2,
                      float* __restrict__ out) {
    extern __shared__ float sm[];
    float* sW = sm;                 // 132*64
    float* sA = sm + 132 * 64;      // 132*64, layout [k][edge]
    int tid = threadIdx.x;
    int eb = blockIdx.x * 64;

    for (int idx = tid; idx < 132 * 64; idx += 256) sW[idx] = Wm1[idx];

    // gather edge inputs: 4 threads per edge, each handles 16 features
    int el = tid & 63;       // edge within tile
    int q  = tid >> 6;       // 0..3 feature quarter
    int e  = eb + el;
    if (e < NE) {
        int s = src[e], d = dst[e];
        const float* hs = g_h + (size_t)s * 64 + q * 16;
        const float* hd = g_h + (size_t)d * 64 + q * 16;
#pragma unroll
        for (int u = 0; u < 16; u++) {
            sA[(q * 16 + u) * 64 + el]      = hs[u];
            sA[(64 + q * 16 + u) * 64 + el] = hd[u];
        }
        if (q == 0) {
            float4 a = *reinterpret_cast<const float4*>(ea + (size_t)e * 4);
            sA[128 * 64 + el] = a.x;
            sA[129 * 64 + el] = a.y;
            sA[130 * 64 + el] = a.z;
            sA[131 * 64 + el] = a.w;
        }
    }
    __syncthreads();

    int cg = tid & 15, c0 = cg * 4;    // 16 col-groups x 4 cols
    int eg = tid >> 4, e0 = eg * 4;    // 16 edge-groups x 4 edges
    float acc[4][4] = {};
#pragma unroll 4
    for (int k = 0; k < 132; k++) {
        float4 a = *reinterpret_cast<float4*>(&sA[k * 64 + e0]);
        float4 b = *reinterpret_cast<float4*>(&sW[k * 64 + c0]);
        acc[0][0] += a.x * b.x; acc[0][1] += a.x * b.y; acc[0][2] += a.x * b.z; acc[0][3] += a.x * b.w;
        acc[1][0] += a.y * b.x; acc[1][1] += a.y * b.y; acc[1][2] += a.y * b.z; acc[1][3] += a.y * b.w;
        acc[2][0] += a.z * b.x; acc[2][1] += a.z * b.y; acc[2][2] += a.z * b.z; acc[2][3] += a.z * b.w;
        acc[3][0] += a.w * b.x; acc[3][1] += a.w * b.y; acc[3][2] += a.w * b.z; acc[3][3] += a.w * b.w;
    }

    // epilogue: relu(+bm1) then dot with Wm2 segment, reduce over 16 col-groups
    float bseg[4], wseg[4];
#pragma unroll
    for (int j = 0; j < 4; j++) {
        bseg[j] = __ldg(bm1 + c0 + j);
        wseg[j] = __ldg(Wm2 + c0 + j);
    }
    float part[4];
#pragma unroll
    for (int i = 0; i < 4; i++) {
        float p = 0.f;
#pragma unroll
        for (int j = 0; j < 4; j++) {
            float z = acc[i][j] + bseg[j];
            z = z > 0.f ? z : 0.f;
            p += z * wseg[j];
        }
        part[i] = p;
    }
    // reduce across the 16 lanes of each half-warp (cg dimension)
#pragma unroll
    for (int off = 8; off >= 1; off >>= 1) {
#pragma unroll
        for (int i = 0; i < 4; i++)
            part[i] += __shfl_down_sync(0xffffffffu, part[i], off);
    }
    if (cg == 0) {
        float bb = __ldg(bm2);
#pragma unroll
        for (int i = 0; i < 4; i++) {
            int eo = eb + e0 + i;
            if (eo < NE) out[eo] = part[i] + bb;
        }
    }
}

extern "C" void kernel_launch(void* const* d_in, const int* in_sizes, int n_in,
                              void* d_out, int out_size) {
    const float* x   = (const float*)d_in[0];
    const int*   ei  = (const int*)  d_in[1];   // [2, NE] int32
    const float* ea  = (const float*)d_in[2];
    const float* W1  = (const float*)d_in[3];
    const float* b1  = (const float*)d_in[4];
    const float* W2  = (const float*)d_in[5];
    const float* b2  = (const float*)d_in[6];
    const float* Wm1 = (const float*)d_in[7];
    const float* bm1 = (const float*)d_in[8];
    const float* Wm2 = (const float*)d_in[9];
    const float* bm2 = (const float*)d_in[10];
    float* out = (float*)d_out;

    const int* src = ei;
    const int* dst = ei + NE;

    const int MLP_SMEM = 2 * 132 * 64 * (int)sizeof(float);  // 67584 B
    cudaFuncSetAttribute(k_mlp, cudaFuncAttributeMaxDynamicSharedMemorySize, MLP_SMEM);

    const int TB = 256;
    long long scat_threads = (long long)NE * H;
    int scat_blocks = (int)((scat_threads + TB - 1) / TB);

    // norm
    k_init_deg<<<(NN + TB - 1) / TB, TB>>>();
    k_deg<<<(NE + TB - 1) / TB, TB>>>(dst);
    k_dis<<<(NN + TB - 1) / TB, TB>>>();

    // layer 1
    k_xw1<<<(NN * H + TB - 1) / TB, TB>>>(x, W1);
    k_scatter<<<scat_blocks, TB>>>(src, dst);
    k_relu_bias<<<(NN * H + TB - 1) / TB, TB>>>(b1);

    // layer 2
    k_gemm2<<<NN / 16, TB>>>(W2);               // 100000 % 16 == 0
    k_scatter<<<scat_blocks, TB>>>(src, dst);
    k_relu_bias<<<(NN * H + TB - 1) / TB, TB>>>(b2);

    // edge MLP
    k_mlp<<<(NE + 63) / 64, TB, MLP_SMEM>>>(src, dst, ea, Wm1, bm1, Wm2, bm2, out);
}

// round 3
// speedup vs baseline: 4.8248x; 4.8248x over previous
#include <cuda_runtime.h>

#define NN 100000
#define NE 3200000
#define H  64

// -------- device scratch (no allocations allowed) --------
__device__ int   g_cnt[NN];
__device__ int   g_row[NN + 1];
__device__ int   g_pos[NN];
__device__ float g_dis[NN];
__device__ int   g_cs[NE];      // CSR: src node per slot
__device__ float g_cw[NE];      // CSR: dis[s]*dis[d] per slot
__device__ float g_tmp[NN * H]; // pre-aggregation messages (x@W)
__device__ float g_h  [NN * H]; // node features after each layer
__device__ float g_P  [NN * H]; // h2 @ Wm1[0:64]
__device__ float g_Q  [NN * H]; // h2 @ Wm1[64:128]

// -------- CSR build --------
__global__ void k_zero_cnt() {
    int i = blockIdx.x * blockDim.x + threadIdx.x;
    if (i < NN) g_cnt[i] = 0;
}

__global__ void k_hist(const int* __restrict__ dst) {
    int e = blockIdx.x * blockDim.x + threadIdx.x;
    if (e < NE) atomicAdd(&g_cnt[dst[e]], 1);
}

__global__ void k_dis() {
    int i = blockIdx.x * blockDim.x + threadIdx.x;
    if (i < NN) g_dis[i] = rsqrtf((float)(g_cnt[i] + 1));  // +1 self-loop
}

// single-block exclusive scan of g_cnt -> g_row / g_pos
__global__ void k_scan() {
    __shared__ int ss[1024];
    int t = threadIdx.x;
    const int per = (NN + 1023) >> 10;           // 98
    int b = t * per;
    int e = b + per; if (e > NN) e = NN;
    if (b > NN) b = NN;
    int loc = 0;
    for (int i = b; i < e; i++) loc += g_cnt[i];
    ss[t] = loc;
    __syncthreads();
    for (int off = 1; off < 1024; off <<= 1) {
        int v = (t >= off) ? ss[t - off] : 0;
        __syncthreads();
        ss[t] += v;
        __syncthreads();
    }
    int run = ss[t] - loc;                        // exclusive prefix
    for (int i = b; i < e; i++) {
        int c = g_cnt[i];
        g_row[i] = run;
        g_pos[i] = run;
        run += c;
    }
    if (t == 1023) g_row[NN] = ss[1023];          // == NE
}

__global__ void k_place(const int* __restrict__ src, const int* __restrict__ dst) {
    int e = blockIdx.x * blockDim.x + threadIdx.x;
    if (e >= NE) return;
    int s = src[e], d = dst[e];
    int idx = atomicAdd(&g_pos[d], 1);
    g_cs[idx] = s;
    g_cw[idx] = g_dis[s] * g_dis[d];
}

// -------- layer 1 dense: tmp = x @ W1 --------
__global__ void k_xw1(const float* __restrict__ x, const float* __restrict__ W1) {
    int t = blockIdx.x * blockDim.x + threadIdx.x;
    if (t >= NN * H) return;
    int i = t >> 6, j = t & 63;
    float4 xv = *reinterpret_cast<const float4*>(x + (size_t)i * 4);
    g_tmp[t] = xv.x * W1[j] + xv.y * W1[64 + j] + xv.z * W1[128 + j] + xv.w * W1[192 + j];
}

// -------- aggregation: g_h[n] = relu( sum_in-edges g_tmp[s]*w + g_tmp[n]*dis[n]^2 + b ) --------
// one warp per node, 2 feature columns per lane.
// NOTE: g_tmp / g_h referenced directly from device code (NOT passed from host
// -- host-side __device__ symbol addresses are the shadow object, and with
// ATS/pageableMemoryAccess the kernel silently reads host memory).
__global__ void k_agg(const float* __restrict__ bias) {
    int w = (blockIdx.x * blockDim.x + threadIdx.x) >> 5;
    if (w >= NN) return;
    int lane = threadIdx.x & 31;
    int r = g_row[w], r1 = g_row[w + 1];
    float a0 = 0.f, a1 = 0.f;
    for (; r + 1 < r1; r += 2) {
        int   s0 = g_cs[r],     s1 = g_cs[r + 1];
        float w0 = g_cw[r],     w1 = g_cw[r + 1];
        const float* p0 = g_tmp + (size_t)s0 * H;
        const float* p1 = g_tmp + (size_t)s1 * H;
        float x00 = p0[lane], x01 = p0[lane + 32];
        float x10 = p1[lane], x11 = p1[lane + 32];
        a0 += x00 * w0; a1 += x01 * w0;
        a0 += x10 * w1; a1 += x11 * w1;
    }
    if (r < r1) {
        int s = g_cs[r]; float ww = g_cw[r];
        const float* p = g_tmp + (size_t)s * H;
        a0 += p[lane] * ww; a1 += p[lane + 32] * ww;
    }
    float dd = g_dis[w]; dd *= dd;                  // self-loop
    const float* p = g_tmp + (size_t)w * H;
    a0 += p[lane] * dd;      a1 += p[lane + 32] * dd;
    a0 += bias[lane];        a1 += bias[lane + 32];
    size_t o = (size_t)w * H;
    g_h[o + lane]      = fmaxf(a0, 0.f);
    g_h[o + lane + 32] = fmaxf(a1, 0.f);
}

// -------- layer 2 dense: tmp = h @ W2 (16 nodes / block) --------
__global__ void k_gemm2(const float* __restrict__ W2) {
    __shared__ float sW[4096];
    __shared__ float sIn[1024];
    int tid = threadIdx.x;
    int nb = blockIdx.x * 16;
    for (int i = tid; i < 4096; i += 256) sW[i] = W2[i];
    for (int i = tid; i < 1024; i += 256) sIn[i] = g_h[nb * 64 + i];
    __syncthreads();
    int col = tid & 63, ng = tid >> 6;
    float a[4] = {0.f, 0.f, 0.f, 0.f};
#pragma unroll 8
    for (int k = 0; k < 64; k++) {
        float w = sW[k * 64 + col];
#pragma unroll
        for (int m = 0; m < 4; m++) a[m] += sIn[(ng + 4 * m) * 64 + k] * w;
    }
#pragma unroll
    for (int m = 0; m < 4; m++)
        g_tmp[(size_t)(nb + ng + 4 * m) * 64 + col] = a[m];
}

// -------- P = h @ Wm1[0:64], Q = h @ Wm1[64:128] --------
__global__ void k_gemmPQ(const float* __restrict__ Wm1) {
    __shared__ float sWa[4096];
    __shared__ float sWb[4096];
    __shared__ float sIn[1024];
    int tid = threadIdx.x;
    int nb = blockIdx.x * 16;
    for (int i = tid; i < 4096; i += 256) { sWa[i] = Wm1[i]; sWb[i] = Wm1[4096 + i]; }
    for (int i = tid; i < 1024; i += 256) sIn[i] = g_h[nb * 64 + i];
    __syncthreads();
    int col = tid & 63, ng = tid >> 6;
    float p[4] = {0.f, 0.f, 0.f, 0.f};
    float q[4] = {0.f, 0.f, 0.f, 0.f};
#pragma unroll 8
    for (int k = 0; k < 64; k++) {
        float wa = sWa[k * 64 + col];
        float wb = sWb[k * 64 + col];
#pragma unroll
        for (int m = 0; m < 4; m++) {
            float xv = sIn[(ng + 4 * m) * 64 + k];
            p[m] += xv * wa;
            q[m] += xv * wb;
        }
    }
#pragma unroll
    for (int m = 0; m < 4; m++) {
        size_t o = (size_t)(nb + ng + 4 * m) * 64 + col;
        g_P[o] = p[m];
        g_Q[o] = q[m];
    }
}

// -------- edge epilogue: out[e] = relu(P[s]+Q[d]+ea@Wea+bm1) @ Wm2 + bm2 --------
// 16 lanes per edge, grid-stride; weights hoisted to registers.
__global__ void k_edge(const int* __restrict__ src, const int* __restrict__ dst,
                       const float* __restrict__ ea,
                       const float* __restrict__ Wm1, const float* __restrict__ bm1,
                       const float* __restrict__ Wm2, const float* __restrict__ bm2,
                       float* __restrict__ out) {
    int l  = threadIdx.x & 15;
    int c0 = l * 4;
    float4 w0 = *reinterpret_cast<const float4*>(Wm1 + 128 * 64 + c0);
    float4 w1 = *reinterpret_cast<const float4*>(Wm1 + 129 * 64 + c0);
    float4 w2 = *reinterpret_cast<const float4*>(Wm1 + 130 * 64 + c0);
    float4 w3 = *reinterpret_cast<const float4*>(Wm1 + 131 * 64 + c0);
    float4 bb = *reinterpret_cast<const float4*>(bm1 + c0);
    float4 wo = *reinterpret_cast<const float4*>(Wm2 + c0);
    float  ob = bm2[0];

    int grp  = (blockIdx.x * blockDim.x + threadIdx.x) >> 4;
    int ngrp = (gridDim.x * blockDim.x) >> 4;
    for (int e = grp; e < NE; e += ngrp) {
        int s = src[e], d = dst[e];
        float4 p = *reinterpret_cast<const float4*>(g_P + (size_t)s * 64 + c0);
        float4 q = *reinterpret_cast<const float4*>(g_Q + (size_t)d * 64 + c0);
        float4 a = *reinterpret_cast<const float4*>(ea + (size_t)e * 4);
        float z0 = p.x + q.x + bb.x + a.x * w0.x + a.y * w1.x + a.z * w2.x + a.w * w3.x;
        float z1 = p.y + q.y + bb.y + a.x * w0.y + a.y * w1.y + a.z * w2.y + a.w * w3.y;
        float z2 = p.z + q.z + bb.z + a.x * w0.z + a.y * w1.z + a.z * w2.z + a.w * w3.z;
        float z3 = p.w + q.w + bb.w + a.x * w0.w + a.y * w1.w + a.z * w2.w + a.w * w3.w;
        z0 = fmaxf(z0, 0.f); z1 = fmaxf(z1, 0.f); z2 = fmaxf(z2, 0.f); z3 = fmaxf(z3, 0.f);
        float part = z0 * wo.x + z1 * wo.y + z2 * wo.z + z3 * wo.w;
#pragma unroll
        for (int off = 8; off >= 1; off >>= 1)
            part += __shfl_down_sync(0xffffffffu, part, off, 16);
        if (l == 0) out[e] = part + ob;
    }
}

extern "C" void kernel_launch(void* const* d_in, const int* in_sizes, int n_in,
                              void* d_out, int out_size) {
    const float* x   = (const float*)d_in[0];
    const int*   ei  = (const int*)  d_in[1];   // [2, NE] int32
    const float* ea  = (const float*)d_in[2];
    const float* W1  = (const float*)d_in[3];
    const float* b1  = (const float*)d_in[4];
    const float* W2  = (const float*)d_in[5];
    const float* b2  = (const float*)d_in[6];
    const float* Wm1 = (const float*)d_in[7];
    const float* bm1 = (const float*)d_in[8];
    const float* Wm2 = (const float*)d_in[9];
    const float* bm2 = (const float*)d_in[10];
    float* out = (float*)d_out;

    const int* src = ei;
    const int* dst = ei + NE;

    const int TB = 256;
    int nn_blk  = (NN + TB - 1) / TB;
    int ne_blk  = (NE + TB - 1) / TB;
    int nnh_blk = (NN * H + TB - 1) / TB;
    int agg_blk = (NN + 7) / 8;                  // 8 nodes (warps) per block

    // CSR build + norm
    k_zero_cnt<<<nn_blk, TB>>>();
    k_hist<<<ne_blk, TB>>>(dst);
    k_dis<<<nn_blk, TB>>>();
    k_scan<<<1, 1024>>>();
    k_place<<<ne_blk, TB>>>(src, dst);

    // layer 1
    k_xw1<<<nnh_blk, TB>>>(x, W1);
    k_agg<<<agg_blk, TB>>>(b1);

    // layer 2
    k_gemm2<<<NN / 16, TB>>>(W2);
    k_agg<<<agg_blk, TB>>>(b2);

    // edge MLP (factored through nodes)
    k_gemmPQ<<<NN / 16, TB>>>(Wm1);
    k_edge<<<1184, TB>>>(src, dst, ea, Wm1, bm1, Wm2, bm2, out);
}